// round 1
// baseline (speedup 1.0000x reference)
#include <cuda_runtime.h>
#include <cuda_bf16.h>
#include <cstdint>

// Problem constants
#define BB 4
#define TT 1024
#define CC 1024
#define HH 16
#define HS 64
#define LL 12
#define VV 50304
#define NN (BB*TT)          // 4096 tokens
#define FF (4*CC)           // 4096

// ---------------- scratch (device globals; no allocation allowed) -----------
__device__ float g_x[NN*CC];
__device__ float g_h[NN*CC];
__device__ float g_q[NN*CC];
__device__ float g_k[NN*CC];
__device__ float g_v[NN*CC];
__device__ float g_att[NN*CC];
__device__ float g_ffh[(size_t)NN*FF];
__device__ float g_S[(size_t)BB*HH*TT*TT];      // 268 MB attention scores
__device__ float g_rowloss[NN + 4];
__device__ float g_logits_fb[(size_t)NN*VV];    // fallback if d_out too small

// ---------------- reductions ------------------------------------------------
__device__ __forceinline__ float block_reduce_sum(float v, float* buf) {
    int tid = threadIdx.x;
    buf[tid] = v; __syncthreads();
    for (int s = 128; s > 0; s >>= 1) {
        if (tid < s) buf[tid] += buf[tid + s];
        __syncthreads();
    }
    float r = buf[0]; __syncthreads();
    return r;
}
__device__ __forceinline__ float block_reduce_max(float v, float* buf) {
    int tid = threadIdx.x;
    buf[tid] = v; __syncthreads();
    for (int s = 128; s > 0; s >>= 1) {
        if (tid < s) buf[tid] = fmaxf(buf[tid], buf[tid + s]);
        __syncthreads();
    }
    float r = buf[0]; __syncthreads();
    return r;
}

// ---------------- embedding -------------------------------------------------
__global__ __launch_bounds__(256) void embed_kernel(
    const int* __restrict__ idx, const float* __restrict__ tok,
    const float* __restrict__ pos, float* __restrict__ x)
{
    size_t i = (size_t)blockIdx.x * 256 + threadIdx.x;   // over NN*CC
    int n = (int)(i >> 10);
    int c = (int)(i & 1023);
    int t = n & (TT - 1);
    x[i] = tok[(size_t)idx[n] * CC + c] + pos[(size_t)t * CC + c];
}

// ---------------- layernorm -------------------------------------------------
__global__ __launch_bounds__(256) void ln_kernel(
    const float* __restrict__ x, const float* __restrict__ g,
    const float* __restrict__ b, float* __restrict__ out)
{
    __shared__ float buf[256];
    int row = blockIdx.x;
    const float* xr = x + (size_t)row * CC;
    float s = 0.f, ss = 0.f;
    for (int c = threadIdx.x; c < CC; c += 256) {
        float v = xr[c]; s += v; ss += v * v;
    }
    s  = block_reduce_sum(s, buf);
    ss = block_reduce_sum(ss, buf);
    float mu  = s * (1.f / CC);
    float inv = rsqrtf(ss * (1.f / CC) - mu * mu + 1e-5f);
    float* orow = out + (size_t)row * CC;
    for (int c = threadIdx.x; c < CC; c += 256)
        orow[c] = (xr[c] - mu) * inv * g[c] + b[c];
}

// ---------------- SGEMM: C = A[M,K] @ W[K,N] (+bias)(+relu)(+res) -----------
// tiles 128x128x8, 256 threads, 8x8 microtile. M%128==0, N%128==0, K%8==0.
__global__ __launch_bounds__(256) void sgemm_kernel(
    const float* __restrict__ A, const float* __restrict__ Bw,
    const float* __restrict__ bias, const float* __restrict__ res,
    float* __restrict__ C, int M, int N, int K, int relu)
{
    __shared__ float As[8][132];
    __shared__ float Bs[8][128];
    int tid = threadIdx.x;
    int m0 = blockIdx.y << 7, n0 = blockIdx.x << 7;
    int arow = tid >> 1, acol = (tid & 1) << 2;
    int brow = tid >> 5, bcol = (tid & 31) << 2;
    int ty = tid >> 4, tx = tid & 15;
    const float* Aptr = A + (size_t)(m0 + arow) * K + acol;
    const float* Bptr = Bw + (size_t)brow * N + n0 + bcol;
    float acc[8][8] = {};
    for (int k0 = 0; k0 < K; k0 += 8) {
        float4 av = *(const float4*)(Aptr + k0);
        As[acol + 0][arow] = av.x; As[acol + 1][arow] = av.y;
        As[acol + 2][arow] = av.z; As[acol + 3][arow] = av.w;
        float4 bv = *(const float4*)(Bptr + (size_t)k0 * N);
        *(float4*)&Bs[brow][bcol] = bv;
        __syncthreads();
#pragma unroll
        for (int kk = 0; kk < 8; kk++) {
            float a[8], b[8];
            *(float4*)(a)     = *(const float4*)&As[kk][ty << 3];
            *(float4*)(a + 4) = *(const float4*)&As[kk][(ty << 3) + 4];
            *(float4*)(b)     = *(const float4*)&Bs[kk][tx << 3];
            *(float4*)(b + 4) = *(const float4*)&Bs[kk][(tx << 3) + 4];
#pragma unroll
            for (int i = 0; i < 8; i++)
#pragma unroll
                for (int j = 0; j < 8; j++)
                    acc[i][j] = fmaf(a[i], b[j], acc[i][j]);
        }
        __syncthreads();
    }
#pragma unroll
    for (int i = 0; i < 8; i++) {
        size_t row = (size_t)(m0 + (ty << 3) + i);
        float* crow = C + row * N + n0 + (tx << 3);
        const float* rrow = res ? res + row * N + n0 + (tx << 3) : nullptr;
#pragma unroll
        for (int j = 0; j < 8; j++) {
            float v = acc[i][j];
            if (bias) v += bias[n0 + (tx << 3) + j];
            if (relu) v = fmaxf(v, 0.f);
            if (rrow) v += rrow[j];
            crow[j] = v;
        }
    }
}

// ---------------- attention: S = scale * Q @ K^T (batched, causal tiles) ----
__global__ __launch_bounds__(256) void attn_scores(
    const float* __restrict__ q, const float* __restrict__ k,
    float* __restrict__ S)
{
    int jt = blockIdx.x, it = blockIdx.y, bh = blockIdx.z;
    if (jt > it) return;
    int b = bh >> 4, h = bh & 15;
    const float* Qb = q + ((size_t)b * TT + (size_t)it * 64) * CC + h * 64;
    const float* Kb = k + ((size_t)b * TT + (size_t)jt * 64) * CC + h * 64;
    __shared__ float Qs[64][65];
    __shared__ float Ks[64][65];
    int tid = threadIdx.x;
#pragma unroll
    for (int p = 0; p < 4; p++) {
        int id4 = p * 256 + tid;
        int r = id4 >> 4;
        int c4 = (id4 & 15) << 2;
        float4 qv = *(const float4*)(Qb + (size_t)r * CC + c4);
        Qs[r][c4] = qv.x; Qs[r][c4+1] = qv.y; Qs[r][c4+2] = qv.z; Qs[r][c4+3] = qv.w;
        float4 kv = *(const float4*)(Kb + (size_t)r * CC + c4);
        Ks[r][c4] = kv.x; Ks[r][c4+1] = kv.y; Ks[r][c4+2] = kv.z; Ks[r][c4+3] = kv.w;
    }
    __syncthreads();
    int ty = tid >> 4, tx = tid & 15;
    float acc[4][4] = {};
#pragma unroll 4
    for (int d = 0; d < 64; d++) {
        float a[4], bb[4];
#pragma unroll
        for (int i = 0; i < 4; i++) a[i]  = Qs[(ty << 2) + i][d];
#pragma unroll
        for (int j = 0; j < 4; j++) bb[j] = Ks[(tx << 2) + j][d];
#pragma unroll
        for (int i = 0; i < 4; i++)
#pragma unroll
            for (int j = 0; j < 4; j++)
                acc[i][j] = fmaf(a[i], bb[j], acc[i][j]);
    }
    float* Sp = S + (size_t)bh * TT * TT;
#pragma unroll
    for (int i = 0; i < 4; i++) {
        int row = it * 64 + (ty << 2) + i;
#pragma unroll
        for (int j = 0; j < 4; j++)
            Sp[(size_t)row * TT + jt * 64 + (tx << 2) + j] = acc[i][j] * 0.125f;
    }
}

// ---------------- causal softmax over rows of S ------------------------------
__global__ __launch_bounds__(256) void attn_softmax(float* __restrict__ S)
{
    __shared__ float buf[256];
    int i = blockIdx.x, bh = blockIdx.y;
    float* row = S + (size_t)bh * TT * TT + (size_t)i * TT;
    int len = i + 1;
    float m = -3.4e38f;
    for (int j = threadIdx.x; j < len; j += 256) m = fmaxf(m, row[j]);
    m = block_reduce_max(m, buf);
    float s = 0.f;
    for (int j = threadIdx.x; j < len; j += 256) {
        float e = __expf(row[j] - m);
        row[j] = e; s += e;
    }
    s = block_reduce_sum(s, buf);
    float inv = 1.f / s;
    for (int j = threadIdx.x; j < len; j += 256) row[j] *= inv;
    int lim = ((i >> 6) + 1) << 6;   // zero ragged edge of diagonal tile only
    for (int j = len + threadIdx.x; j < lim; j += 256) row[j] = 0.f;
}

// ---------------- O = P @ V (batched, K limited by causality) ----------------
__global__ __launch_bounds__(256) void attn_pv(
    const float* __restrict__ S, const float* __restrict__ v,
    float* __restrict__ o)
{
    int it = blockIdx.x, bh = blockIdx.y;
    int b = bh >> 4, h = bh & 15;
    const float* P  = S + (size_t)bh * TT * TT + (size_t)it * 64 * TT;
    const float* Vb = v + (size_t)b * TT * CC + h * 64;
    float* Ob = o + ((size_t)b * TT + (size_t)it * 64) * CC + h * 64;
    __shared__ float Ps[64][17];
    __shared__ float Vs[16][64];
    int tid = threadIdx.x, ty = tid >> 4, tx = tid & 15;
    float acc[4][4] = {};
    int kend = (it + 1) * 64;
    int pr = tid >> 2,  pc4 = (tid & 3) << 2;
    int vr = tid >> 4,  vc4 = (tid & 15) << 2;
    for (int k0 = 0; k0 < kend; k0 += 16) {
        float4 pv = *(const float4*)(P + (size_t)pr * TT + k0 + pc4);
        Ps[pr][pc4] = pv.x; Ps[pr][pc4+1] = pv.y; Ps[pr][pc4+2] = pv.z; Ps[pr][pc4+3] = pv.w;
        *(float4*)&Vs[vr][vc4] = *(const float4*)(Vb + (size_t)(k0 + vr) * CC + vc4);
        __syncthreads();
#pragma unroll
        for (int kk = 0; kk < 16; kk++) {
            float a[4], bb[4];
#pragma unroll
            for (int i = 0; i < 4; i++) a[i]  = Ps[(ty << 2) + i][kk];
#pragma unroll
            for (int j = 0; j < 4; j++) bb[j] = Vs[kk][(tx << 2) + j];
#pragma unroll
            for (int i = 0; i < 4; i++)
#pragma unroll
                for (int j = 0; j < 4; j++)
                    acc[i][j] = fmaf(a[i], bb[j], acc[i][j]);
        }
        __syncthreads();
    }
#pragma unroll
    for (int i = 0; i < 4; i++)
#pragma unroll
        for (int j = 0; j < 4; j++)
            Ob[(size_t)((ty << 2) + i) * CC + (tx << 2) + j] = acc[i][j];
}

// ---------------- loss -------------------------------------------------------
__global__ __launch_bounds__(256) void row_loss_kernel(
    const float* __restrict__ logits, const int* __restrict__ targets,
    float* __restrict__ rl)
{
    __shared__ float buf[256];
    int row = blockIdx.x;
    const float* lr = logits + (size_t)row * VV;
    float m = -3.4e38f;
    for (int j = threadIdx.x; j < VV; j += 256) m = fmaxf(m, lr[j]);
    m = block_reduce_max(m, buf);
    float s = 0.f;
    for (int j = threadIdx.x; j < VV; j += 256) s += __expf(lr[j] - m);
    s = block_reduce_sum(s, buf);
    if (threadIdx.x == 0) {
        int t = targets[row];
        rl[row] = -(lr[t] - m - logf(s));
    }
}

__global__ __launch_bounds__(256) void loss_reduce_kernel(
    const float* __restrict__ rl, float* __restrict__ out)
{
    __shared__ float buf[256];
    float s = 0.f;
    for (int i = threadIdx.x; i < NN; i += 256) s += rl[i];
    s = block_reduce_sum(s, buf);
    if (threadIdx.x == 0) out[0] = s * (1.f / NN);
}

// ---------------- host orchestration ----------------------------------------
static inline void run_gemm(const float* A, const float* W, const float* bias,
                            const float* res, float* C, int M, int N, int K, int relu)
{
    dim3 grid(N / 128, M / 128);
    sgemm_kernel<<<grid, 256>>>(A, W, bias, res, C, M, N, K, relu);
}

extern "C" void kernel_launch(void* const* d_in, const int* in_sizes, int n_in,
                              void* d_out, int out_size)
{
    const int*   idx     = (const int*)  d_in[0];
    const int*   targets = (const int*)  d_in[1];
    const float* tok     = (const float*)d_in[2];
    const float* pos     = (const float*)d_in[3];
    const float* ln1_g   = (const float*)d_in[4];
    const float* ln1_b   = (const float*)d_in[5];
    const float* Wq      = (const float*)d_in[6];
    const float* Wk      = (const float*)d_in[7];
    const float* Wv      = (const float*)d_in[8];
    const float* Wo      = (const float*)d_in[9];
    const float* bo      = (const float*)d_in[10];
    const float* ln2_g   = (const float*)d_in[11];
    const float* ln2_b   = (const float*)d_in[12];
    const float* W1      = (const float*)d_in[13];
    const float* b1      = (const float*)d_in[14];
    const float* W2      = (const float*)d_in[15];
    const float* b2      = (const float*)d_in[16];
    const float* lnf_g   = (const float*)d_in[17];
    const float* lnf_b   = (const float*)d_in[18];
    const float* Wlm     = (const float*)d_in[19];
    const float* blm     = (const float*)d_in[20];
    (void)in_sizes; (void)n_in;

    void* p;
    cudaGetSymbolAddress(&p, g_x);      float* x    = (float*)p;
    cudaGetSymbolAddress(&p, g_h);      float* h    = (float*)p;
    cudaGetSymbolAddress(&p, g_q);      float* q    = (float*)p;
    cudaGetSymbolAddress(&p, g_k);      float* k    = (float*)p;
    cudaGetSymbolAddress(&p, g_v);      float* v    = (float*)p;
    cudaGetSymbolAddress(&p, g_att);    float* att  = (float*)p;
    cudaGetSymbolAddress(&p, g_ffh);    float* ffh  = (float*)p;
    cudaGetSymbolAddress(&p, g_S);      float* S    = (float*)p;
    cudaGetSymbolAddress(&p, g_rowloss);float* rl   = (float*)p;
    cudaGetSymbolAddress(&p, g_logits_fb); float* logits_fb = (float*)p;

    const size_t NV = (size_t)NN * VV;
    float* out = (float*)d_out;
    bool big = ((size_t)out_size >= NV);
    float* logits   = big ? out : logits_fb;
    float* loss_dst = ((size_t)out_size > NV) ? out + NV
                    : (big ? rl + NN : out);   // if exactly NV: park loss in scratch

    // embedding
    embed_kernel<<<(NN * CC) / 256, 256>>>(idx, tok, pos, x);

    for (int l = 0; l < LL; l++) {
        const size_t oC  = (size_t)l * CC;
        const size_t oCC = (size_t)l * CC * CC;
        const size_t oCF = (size_t)l * CC * FF;
        const size_t oF  = (size_t)l * FF;

        ln_kernel<<<NN, 256>>>(x, ln1_g + oC, ln1_b + oC, h);
        run_gemm(h, Wq + oCC, nullptr, nullptr, q, NN, CC, CC, 0);
        run_gemm(h, Wk + oCC, nullptr, nullptr, k, NN, CC, CC, 0);
        run_gemm(h, Wv + oCC, nullptr, nullptr, v, NN, CC, CC, 0);

        attn_scores<<<dim3(TT / 64, TT / 64, BB * HH), 256>>>(q, k, S);
        attn_softmax<<<dim3(TT, BB * HH), 256>>>(S);
        attn_pv<<<dim3(TT / 64, BB * HH), 256>>>(S, v, att);

        run_gemm(att, Wo + oCC, bo + oC, x, x, NN, CC, CC, 0);

        ln_kernel<<<NN, 256>>>(x, ln2_g + oC, ln2_b + oC, h);
        run_gemm(h, W1 + oCF, b1 + oF, nullptr, ffh, NN, FF, CC, 1);
        run_gemm(ffh, W2 + oCF, b2 + oC, x, x, NN, CC, FF, 0);
    }

    ln_kernel<<<NN, 256>>>(x, lnf_g, lnf_b, h);
    run_gemm(h, Wlm, blm, nullptr, logits, NN, VV, CC, 0);

    row_loss_kernel<<<NN, 256>>>(logits, targets, rl);
    loss_reduce_kernel<<<1, 256>>>(rl, loss_dst);
}

// round 3
// speedup vs baseline: 2.5589x; 2.5589x over previous
#include <cuda_runtime.h>
#include <cuda_bf16.h>
#include <cstdint>

// Problem constants
#define BB 4
#define TT 1024
#define CC 1024
#define HH 16
#define HS 64
#define LL 12
#define VV 50304
#define NN (BB*TT)          // 4096 tokens
#define FF (4*CC)           // 4096

// ---------------- scratch (device globals; no allocation allowed) -----------
__device__ float g_x[NN*CC];
__device__ float g_h[NN*CC];
__device__ float g_q[NN*CC];
__device__ float g_k[NN*CC];
__device__ float g_v[NN*CC];
__device__ float g_att[NN*CC];
__device__ float g_ffh[(size_t)NN*FF];
__device__ float g_S[(size_t)BB*HH*TT*TT];      // 268 MB attention scores
__device__ float g_rowloss[NN + 4];
__device__ float g_logits_fb[(size_t)NN*VV];    // fallback if d_out too small
// transposed weights [N,K] (tf32-rounded)
__device__ float g_WqT[(size_t)LL*CC*CC];
__device__ float g_WkT[(size_t)LL*CC*CC];
__device__ float g_WvT[(size_t)LL*CC*CC];
__device__ float g_WoT[(size_t)LL*CC*CC];
__device__ float g_W1T[(size_t)LL*CC*FF];
__device__ float g_W2T[(size_t)LL*FF*CC];
__device__ float g_WlmT[(size_t)CC*VV];

// ---------------- helpers ----------------------------------------------------
__device__ __forceinline__ uint32_t smem_u32(const void* p) {
    uint32_t a;
    asm("{ .reg .u64 t; cvta.to.shared.u64 t, %1; cvt.u32.u64 %0, t; }" : "=r"(a) : "l"(p));
    return a;
}
__device__ __forceinline__ float tf32r(float x) {
    uint32_t u; asm("cvt.rna.tf32.f32 %0, %1;" : "=r"(u) : "f"(x));
    return __uint_as_float(u);
}
__device__ __forceinline__ uint32_t swz(uint32_t b) { return b ^ ((b >> 3) & 0x70); }

__device__ __forceinline__ void cp16(void* s, const void* g) {
    uint32_t sa = smem_u32(s);
    asm volatile("cp.async.cg.shared.global [%0], [%1], 16;" :: "r"(sa), "l"(g));
}
#define CP_COMMIT() asm volatile("cp.async.commit_group;" ::: "memory")
#define CP_WAIT(n)  asm volatile("cp.async.wait_group %0;" :: "n"(n) : "memory")

__device__ __forceinline__ void mma_tf32(float* d, const uint32_t* a, const uint32_t* b) {
    asm volatile(
        "mma.sync.aligned.m16n8k8.row.col.f32.tf32.tf32.f32 "
        "{%0,%1,%2,%3}, {%4,%5,%6,%7}, {%8,%9}, {%0,%1,%2,%3};"
        : "+f"(d[0]), "+f"(d[1]), "+f"(d[2]), "+f"(d[3])
        : "r"(a[0]), "r"(a[1]), "r"(a[2]), "r"(a[3]), "r"(b[0]), "r"(b[1]));
}

// ---------------- reductions ------------------------------------------------
__device__ __forceinline__ float block_reduce_sum(float v, float* buf) {
    int tid = threadIdx.x;
    buf[tid] = v; __syncthreads();
    for (int s = 128; s > 0; s >>= 1) {
        if (tid < s) buf[tid] += buf[tid + s];
        __syncthreads();
    }
    float r = buf[0]; __syncthreads();
    return r;
}
__device__ __forceinline__ float block_reduce_max(float v, float* buf) {
    int tid = threadIdx.x;
    buf[tid] = v; __syncthreads();
    for (int s = 128; s > 0; s >>= 1) {
        if (tid < s) buf[tid] = fmaxf(buf[tid], buf[tid + s]);
        __syncthreads();
    }
    float r = buf[0]; __syncthreads();
    return r;
}

// ---------------- transpose: dst[N,K] = src[K,N], tf32-rounded ---------------
__global__ __launch_bounds__(256) void transpose_kernel(
    const float* __restrict__ src, float* __restrict__ dst, int K, int N)
{
    __shared__ float t[32][33];
    size_t zoff = (size_t)blockIdx.z * K * N;
    int n0 = blockIdx.x << 5, k0 = blockIdx.y << 5;
    int tx = threadIdx.x & 31, ty = threadIdx.x >> 5;
#pragma unroll
    for (int p = 0; p < 4; p++)
        t[ty + p * 8][tx] = src[zoff + (size_t)(k0 + ty + p * 8) * N + n0 + tx];
    __syncthreads();
#pragma unroll
    for (int p = 0; p < 4; p++)
        dst[zoff + (size_t)(n0 + ty + p * 8) * K + k0 + tx] = tf32r(t[tx][ty + p * 8]);
}

// ---------------- embedding -------------------------------------------------
__global__ __launch_bounds__(256) void embed_kernel(
    const int* __restrict__ idx, const float* __restrict__ tok,
    const float* __restrict__ pos, float* __restrict__ x)
{
    size_t i = (size_t)blockIdx.x * 256 + threadIdx.x;
    int n = (int)(i >> 10);
    int c = (int)(i & 1023);
    int t = n & (TT - 1);
    x[i] = tok[(size_t)idx[n] * CC + c] + pos[(size_t)t * CC + c];
}

// ---------------- layernorm (tf32-rounded output: used only as GEMM A) ------
__global__ __launch_bounds__(256) void ln_kernel(
    const float* __restrict__ x, const float* __restrict__ g,
    const float* __restrict__ b, float* __restrict__ out)
{
    __shared__ float buf[256];
    int row = blockIdx.x;
    const float* xr = x + (size_t)row * CC;
    float s = 0.f, ss = 0.f;
    for (int c = threadIdx.x; c < CC; c += 256) {
        float v = xr[c]; s += v; ss += v * v;
    }
    s  = block_reduce_sum(s, buf);
    ss = block_reduce_sum(ss, buf);
    float mu  = s * (1.f / CC);
    float inv = rsqrtf(ss * (1.f / CC) - mu * mu + 1e-5f);
    float* orow = out + (size_t)row * CC;
    for (int c = threadIdx.x; c < CC; c += 256)
        orow[c] = tf32r((xr[c] - mu) * inv * g[c] + b[c]);
}

// ---------------- mma.sync tf32 GEMM: C = A[M,K] @ Bt[N,K]^T -----------------
// BM=128, BN=128, BK=32, 256 threads (8 warps, 2x4), 3-stage cp.async pipeline.
#define GEMM_SMEM (3*32768)
__global__ __launch_bounds__(256) void mma_gemm_kernel(
    const float* __restrict__ A, const float* __restrict__ Bt,
    const float* __restrict__ bias, const float* __restrict__ res,
    float* __restrict__ C, int M, int N, int K, int relu)
{
    extern __shared__ char smem[];
    int tid = threadIdx.x;
    int wid = tid >> 5, lane = tid & 31;
    int g = lane >> 2, q = lane & 3;
    int wm0 = (wid >> 2) << 6;      // 0 or 64
    int wn0 = (wid & 3) << 5;       // 0,32,64,96
    int m0 = blockIdx.y << 7, n0 = blockIdx.x << 7;

    const float* Abase = A + (size_t)m0 * K;
    const float* Bbase = Bt + (size_t)n0 * K;
    int Kc = K >> 5;

    float acc[4][4][4] = {};

    // prefetch stages 0,1
#pragma unroll
    for (int c = 0; c < 2; c++) {
        char* sa = smem + c * 32768;
        char* sbm = sa + 16384;
#pragma unroll
        for (int p = 0; p < 4; p++) {
            int id = p * 256 + tid;
            int row = id >> 3, ch = id & 7;
            uint32_t off = swz((row << 7) + (ch << 4));
            cp16(sa + off, Abase + (size_t)row * K + (c << 5) + (ch << 2));
            cp16(sbm + off, Bbase + (size_t)row * K + (c << 5) + (ch << 2));
        }
        CP_COMMIT();
    }

    for (int c = 0; c < Kc; c++) {
        if (c + 2 < Kc) { CP_WAIT(1); } else { CP_WAIT(0); }
        __syncthreads();
        if (c + 2 < Kc) {
            int cs = c + 2;
            char* sa = smem + (cs % 3) * 32768;
            char* sbm = sa + 16384;
#pragma unroll
            for (int p = 0; p < 4; p++) {
                int id = p * 256 + tid;
                int row = id >> 3, ch = id & 7;
                uint32_t off = swz((row << 7) + (ch << 4));
                cp16(sa + off, Abase + (size_t)row * K + (cs << 5) + (ch << 2));
                cp16(sbm + off, Bbase + (size_t)row * K + (cs << 5) + (ch << 2));
            }
            CP_COMMIT();
        }
        const char* As = smem + (c % 3) * 32768;
        const char* Bs = As + 16384;
#pragma unroll
        for (int ks = 0; ks < 4; ks++) {
            int k0 = ks << 3;
            uint32_t af[4][4];
#pragma unroll
            for (int mi = 0; mi < 4; mi++) {
                int r = wm0 + (mi << 4) + g;
                af[mi][0] = *(const uint32_t*)(As + swz((r << 7) + ((k0 + q) << 2)));
                af[mi][1] = *(const uint32_t*)(As + swz(((r + 8) << 7) + ((k0 + q) << 2)));
                af[mi][2] = *(const uint32_t*)(As + swz((r << 7) + ((k0 + q + 4) << 2)));
                af[mi][3] = *(const uint32_t*)(As + swz(((r + 8) << 7) + ((k0 + q + 4) << 2)));
            }
            uint32_t bf[4][2];
#pragma unroll
            for (int ni = 0; ni < 4; ni++) {
                int n = wn0 + (ni << 3) + g;
                bf[ni][0] = *(const uint32_t*)(Bs + swz((n << 7) + ((k0 + q) << 2)));
                bf[ni][1] = *(const uint32_t*)(Bs + swz((n << 7) + ((k0 + q + 4) << 2)));
            }
#pragma unroll
            for (int mi = 0; mi < 4; mi++)
#pragma unroll
                for (int ni = 0; ni < 4; ni++)
                    mma_tf32(acc[mi][ni], af[mi], bf[ni]);
        }
    }

    // epilogue
#pragma unroll
    for (int mi = 0; mi < 4; mi++) {
#pragma unroll
        for (int half = 0; half < 2; half++) {
            int row = m0 + wm0 + (mi << 4) + g + half * 8;
            float* crow = C + (size_t)row * N;
            const float* rrow = res ? res + (size_t)row * N : nullptr;
#pragma unroll
            for (int ni = 0; ni < 4; ni++) {
                int col = n0 + wn0 + (ni << 3) + (q << 1);
                float v0 = acc[mi][ni][half * 2 + 0];
                float v1 = acc[mi][ni][half * 2 + 1];
                if (bias) { v0 += bias[col]; v1 += bias[col + 1]; }
                if (relu) {
                    v0 = tf32r(fmaxf(v0, 0.f));
                    v1 = tf32r(fmaxf(v1, 0.f));
                }
                if (rrow) { v0 += rrow[col]; v1 += rrow[col + 1]; }
                float2 o; o.x = v0; o.y = v1;
                *(float2*)(crow + col) = o;
            }
        }
    }
}

// ---------------- attention: S = scale * Q @ K^T (batched, causal tiles) ----
__global__ __launch_bounds__(256) void attn_scores(
    const float* __restrict__ q, const float* __restrict__ k,
    float* __restrict__ S)
{
    int jt = blockIdx.x, it = blockIdx.y, bh = blockIdx.z;
    if (jt > it) return;
    int b = bh >> 4, h = bh & 15;
    const float* Qb = q + ((size_t)b * TT + (size_t)it * 64) * CC + h * 64;
    const float* Kb = k + ((size_t)b * TT + (size_t)jt * 64) * CC + h * 64;
    __shared__ float Qs[64][65];
    __shared__ float Ks[64][65];
    int tid = threadIdx.x;
#pragma unroll
    for (int p = 0; p < 4; p++) {
        int id4 = p * 256 + tid;
        int r = id4 >> 4;
        int c4 = (id4 & 15) << 2;
        float4 qv = *(const float4*)(Qb + (size_t)r * CC + c4);
        Qs[r][c4] = qv.x; Qs[r][c4+1] = qv.y; Qs[r][c4+2] = qv.z; Qs[r][c4+3] = qv.w;
        float4 kv = *(const float4*)(Kb + (size_t)r * CC + c4);
        Ks[r][c4] = kv.x; Ks[r][c4+1] = kv.y; Ks[r][c4+2] = kv.z; Ks[r][c4+3] = kv.w;
    }
    __syncthreads();
    int ty = tid >> 4, tx = tid & 15;
    float acc[4][4] = {};
#pragma unroll 4
    for (int d = 0; d < 64; d++) {
        float a[4], bb[4];
#pragma unroll
        for (int i = 0; i < 4; i++) a[i]  = Qs[(ty << 2) + i][d];
#pragma unroll
        for (int j = 0; j < 4; j++) bb[j] = Ks[(tx << 2) + j][d];
#pragma unroll
        for (int i = 0; i < 4; i++)
#pragma unroll
            for (int j = 0; j < 4; j++)
                acc[i][j] = fmaf(a[i], bb[j], acc[i][j]);
    }
    float* Sp = S + (size_t)bh * TT * TT;
#pragma unroll
    for (int i = 0; i < 4; i++) {
        int row = it * 64 + (ty << 2) + i;
#pragma unroll
        for (int j = 0; j < 4; j++)
            Sp[(size_t)row * TT + jt * 64 + (tx << 2) + j] = acc[i][j] * 0.125f;
    }
}

// ---------------- causal softmax over rows of S ------------------------------
__global__ __launch_bounds__(256) void attn_softmax(float* __restrict__ S)
{
    __shared__ float buf[256];
    int i = blockIdx.x, bh = blockIdx.y;
    float* row = S + (size_t)bh * TT * TT + (size_t)i * TT;
    int len = i + 1;
    float m = -3.4e38f;
    for (int j = threadIdx.x; j < len; j += 256) m = fmaxf(m, row[j]);
    m = block_reduce_max(m, buf);
    float s = 0.f;
    for (int j = threadIdx.x; j < len; j += 256) {
        float e = __expf(row[j] - m);
        row[j] = e; s += e;
    }
    s = block_reduce_sum(s, buf);
    float inv = 1.f / s;
    for (int j = threadIdx.x; j < len; j += 256) row[j] *= inv;
    int lim = ((i >> 6) + 1) << 6;
    for (int j = len + threadIdx.x; j < lim; j += 256) row[j] = 0.f;
}

// ---------------- O = P @ V (att output tf32-rounded: GEMM A input) ----------
__global__ __launch_bounds__(256) void attn_pv(
    const float* __restrict__ S, const float* __restrict__ v,
    float* __restrict__ o)
{
    int it = blockIdx.x, bh = blockIdx.y;
    int b = bh >> 4, h = bh & 15;
    const float* P  = S + (size_t)bh * TT * TT + (size_t)it * 64 * TT;
    const float* Vb = v + (size_t)b * TT * CC + h * 64;
    float* Ob = o + ((size_t)b * TT + (size_t)it * 64) * CC + h * 64;
    __shared__ float Ps[64][17];
    __shared__ float Vs[16][64];
    int tid = threadIdx.x, ty = tid >> 4, tx = tid & 15;
    float acc[4][4] = {};
    int kend = (it + 1) * 64;
    int pr = tid >> 2,  pc4 = (tid & 3) << 2;
    int vr = tid >> 4,  vc4 = (tid & 15) << 2;
    for (int k0 = 0; k0 < kend; k0 += 16) {
        float4 pv = *(const float4*)(P + (size_t)pr * TT + k0 + pc4);
        Ps[pr][pc4] = pv.x; Ps[pr][pc4+1] = pv.y; Ps[pr][pc4+2] = pv.z; Ps[pr][pc4+3] = pv.w;
        *(float4*)&Vs[vr][vc4] = *(const float4*)(Vb + (size_t)(k0 + vr) * CC + vc4);
        __syncthreads();
#pragma unroll
        for (int kk = 0; kk < 16; kk++) {
            float a[4], bb[4];
#pragma unroll
            for (int i = 0; i < 4; i++) a[i]  = Ps[(ty << 2) + i][kk];
#pragma unroll
            for (int j = 0; j < 4; j++) bb[j] = Vs[kk][(tx << 2) + j];
#pragma unroll
            for (int i = 0; i < 4; i++)
#pragma unroll
                for (int j = 0; j < 4; j++)
                    acc[i][j] = fmaf(a[i], bb[j], acc[i][j]);
        }
        __syncthreads();
    }
#pragma unroll
    for (int i = 0; i < 4; i++)
#pragma unroll
        for (int j = 0; j < 4; j++)
            Ob[(size_t)((ty << 2) + i) * CC + (tx << 2) + j] = tf32r(acc[i][j]);
}

// ---------------- loss -------------------------------------------------------
__global__ __launch_bounds__(256) void row_loss_kernel(
    const float* __restrict__ logits, const int* __restrict__ targets,
    float* __restrict__ rl)
{
    __shared__ float buf[256];
    int row = blockIdx.x;
    const float* lr = logits + (size_t)row * VV;
    float m = -3.4e38f;
    for (int j = threadIdx.x; j < VV; j += 256) m = fmaxf(m, lr[j]);
    m = block_reduce_max(m, buf);
    float s = 0.f;
    for (int j = threadIdx.x; j < VV; j += 256) s += __expf(lr[j] - m);
    s = block_reduce_sum(s, buf);
    if (threadIdx.x == 0) {
        int t = targets[row];
        rl[row] = -(lr[t] - m - logf(s));
    }
}

__global__ __launch_bounds__(256) void loss_reduce_kernel(
    const float* __restrict__ rl, float* __restrict__ out)
{
    __shared__ float buf[256];
    float s = 0.f;
    for (int i = threadIdx.x; i < NN; i += 256) s += rl[i];
    s = block_reduce_sum(s, buf);
    if (threadIdx.x == 0) out[0] = s * (1.f / NN);
}

// ---------------- host orchestration ----------------------------------------
static inline void run_gemm(const float* A, const float* Wt, const float* bias,
                            const float* res, float* C, int M, int N, int K, int relu)
{
    dim3 grid(N / 128, M / 128);
    mma_gemm_kernel<<<grid, 256, GEMM_SMEM>>>(A, Wt, bias, res, C, M, N, K, relu);
}

extern "C" void kernel_launch(void* const* d_in, const int* in_sizes, int n_in,
                              void* d_out, int out_size)
{
    const int*   idx     = (const int*)  d_in[0];
    const int*   targets = (const int*)  d_in[1];
    const float* tok     = (const float*)d_in[2];
    const float* pos     = (const float*)d_in[3];
    const float* ln1_g   = (const float*)d_in[4];
    const float* ln1_b   = (const float*)d_in[5];
    const float* Wq      = (const float*)d_in[6];
    const float* Wk      = (const float*)d_in[7];
    const float* Wv      = (const float*)d_in[8];
    const float* Wo      = (const float*)d_in[9];
    const float* bo      = (const float*)d_in[10];
    const float* ln2_g   = (const float*)d_in[11];
    const float* ln2_b   = (const float*)d_in[12];
    const float* W1      = (const float*)d_in[13];
    const float* b1      = (const float*)d_in[14];
    const float* W2      = (const float*)d_in[15];
    const float* b2      = (const float*)d_in[16];
    const float* lnf_g   = (const float*)d_in[17];
    const float* lnf_b   = (const float*)d_in[18];
    const float* Wlm     = (const float*)d_in[19];
    const float* blm     = (const float*)d_in[20];
    (void)in_sizes; (void)n_in;

    cudaFuncSetAttribute(mma_gemm_kernel,
                         cudaFuncAttributeMaxDynamicSharedMemorySize, GEMM_SMEM);

    void* p;
    cudaGetSymbolAddress(&p, g_x);      float* x    = (float*)p;
    cudaGetSymbolAddress(&p, g_h);      float* h    = (float*)p;
    cudaGetSymbolAddress(&p, g_q);      float* q    = (float*)p;
    cudaGetSymbolAddress(&p, g_k);      float* k    = (float*)p;
    cudaGetSymbolAddress(&p, g_v);      float* v    = (float*)p;
    cudaGetSymbolAddress(&p, g_att);    float* att  = (float*)p;
    cudaGetSymbolAddress(&p, g_ffh);    float* ffh  = (float*)p;
    cudaGetSymbolAddress(&p, g_S);      float* S    = (float*)p;
    cudaGetSymbolAddress(&p, g_rowloss);float* rl   = (float*)p;
    cudaGetSymbolAddress(&p, g_logits_fb); float* logits_fb = (float*)p;
    cudaGetSymbolAddress(&p, g_WqT);    float* WqT  = (float*)p;
    cudaGetSymbolAddress(&p, g_WkT);    float* WkT  = (float*)p;
    cudaGetSymbolAddress(&p, g_WvT);    float* WvT  = (float*)p;
    cudaGetSymbolAddress(&p, g_WoT);    float* WoT  = (float*)p;
    cudaGetSymbolAddress(&p, g_W1T);    float* W1T  = (float*)p;
    cudaGetSymbolAddress(&p, g_W2T);    float* W2T  = (float*)p;
    cudaGetSymbolAddress(&p, g_WlmT);   float* WlmT = (float*)p;

    const size_t NV = (size_t)NN * VV;
    float* out = (float*)d_out;
    bool big = ((size_t)out_size >= NV);
    float* logits   = big ? out : logits_fb;
    float* loss_dst = ((size_t)out_size > NV) ? out + NV
                    : (big ? rl + NN : out);

    // transpose all weights to [N,K] (tf32-rounded)
    transpose_kernel<<<dim3(CC/32, CC/32, LL), 256>>>(Wq, WqT, CC, CC);
    transpose_kernel<<<dim3(CC/32, CC/32, LL), 256>>>(Wk, WkT, CC, CC);
    transpose_kernel<<<dim3(CC/32, CC/32, LL), 256>>>(Wv, WvT, CC, CC);
    transpose_kernel<<<dim3(CC/32, CC/32, LL), 256>>>(Wo, WoT, CC, CC);
    transpose_kernel<<<dim3(FF/32, CC/32, LL), 256>>>(W1, W1T, CC, FF);
    transpose_kernel<<<dim3(CC/32, FF/32, LL), 256>>>(W2, W2T, FF, CC);
    transpose_kernel<<<dim3(VV/32, CC/32, 1),  256>>>(Wlm, WlmT, CC, VV);

    // embedding
    embed_kernel<<<(NN * CC) / 256, 256>>>(idx, tok, pos, x);

    for (int l = 0; l < LL; l++) {
        const size_t oC  = (size_t)l * CC;
        const size_t oCC = (size_t)l * CC * CC;
        const size_t oCF = (size_t)l * CC * FF;
        const size_t oF  = (size_t)l * FF;

        ln_kernel<<<NN, 256>>>(x, ln1_g + oC, ln1_b + oC, h);
        run_gemm(h, WqT + oCC, nullptr, nullptr, q, NN, CC, CC, 0);
        run_gemm(h, WkT + oCC, nullptr, nullptr, k, NN, CC, CC, 0);
        run_gemm(h, WvT + oCC, nullptr, nullptr, v, NN, CC, CC, 0);

        attn_scores<<<dim3(TT / 64, TT / 64, BB * HH), 256>>>(q, k, S);
        attn_softmax<<<dim3(TT, BB * HH), 256>>>(S);
        attn_pv<<<dim3(TT / 64, BB * HH), 256>>>(S, v, att);

        run_gemm(att, WoT + oCC, bo + oC, x, x, NN, CC, CC, 0);

        ln_kernel<<<NN, 256>>>(x, ln2_g + oC, ln2_b + oC, h);
        run_gemm(h, W1T + oCF, b1 + oF, nullptr, ffh, NN, FF, CC, 1);
        run_gemm(ffh, W2T + oCF, b2 + oC, x, x, NN, CC, FF, 0);
    }

    ln_kernel<<<NN, 256>>>(x, lnf_g, lnf_b, h);
    run_gemm(h, WlmT, blm, nullptr, logits, NN, VV, CC, 0);

    row_loss_kernel<<<NN, 256>>>(logits, targets, rl);
    loss_reduce_kernel<<<1, 256>>>(rl, loss_dst);
}